// round 10
// baseline (speedup 1.0000x reference)
#include <cuda_runtime.h>
#include <cuda_fp16.h>
#include <cstdint>

// ---------------------------------------------------------------------------
// SelfAttention via mma.sync (HMMA) fp16-emulated-fp32 GEMMs.
// Q/K path: hi+lo fp16 planes, 3 pair-products (~2^-22).
// V proj:   x_hi @ (Wv_hi + Wv_lo), 2 pairs (dropped x_lo term ~1e-4 rel).
// PV path:  fp16 P (normalized by rounded sum) @ split V, 2 pairs.
// QK^T epilogue stores pre-scaled logits + atomic row maxes -> 1-pass softmax.
// ---------------------------------------------------------------------------

constexpr int SEQ = 4096;
constexpr int DIM = 1024;

__device__ __half g_x2[2][(size_t)SEQ * DIM];
__device__ __half g_Wq2[2][(size_t)DIM * DIM];   // transposed [out][in]
__device__ __half g_Wk2[2][(size_t)DIM * DIM];
__device__ __half g_Wv2[2][(size_t)DIM * DIM];
__device__ __half g_Q2[2][(size_t)SEQ * DIM];
__device__ __half g_K2[2][(size_t)SEQ * DIM];
__device__ float  g_V[(size_t)SEQ * DIM];
__device__ __half g_Vt2[2][(size_t)DIM * SEQ];   // [dim][seq]
__device__ float  g_P[(size_t)SEQ * SEQ];        // scaled logits
__device__ __half g_Ph[(size_t)SEQ * SEQ];       // fp16 unnormalized probs
__device__ float  g_rinv[SEQ];
__device__ float  g_rowmax[SEQ];

// ---------------- helpers ---------------------------------------------------
__device__ __forceinline__ uint32_t smem_u32(const void* p) {
    uint32_t a;
    asm("{ .reg .u64 t; cvta.to.shared.u64 t, %1; cvt.u32.u64 %0, t; }"
        : "=r"(a) : "l"(p));
    return a;
}
__device__ __forceinline__ void cp16(uint32_t s, const void* g) {
    asm volatile("cp.async.cg.shared.global [%0], [%1], 16;" :: "r"(s), "l"(g));
}
#define CP_COMMIT() asm volatile("cp.async.commit_group;" ::: "memory")
#define CP_WAIT2()  asm volatile("cp.async.wait_group 2;" ::: "memory")
#define CP_WAIT1()  asm volatile("cp.async.wait_group 1;" ::: "memory")
#define CP_WAIT0()  asm volatile("cp.async.wait_group 0;" ::: "memory")

__device__ __forceinline__ void ldsm4(uint32_t* r, uint32_t addr) {
    asm volatile("ldmatrix.sync.aligned.m8n8.x4.shared.b16 {%0,%1,%2,%3}, [%4];"
                 : "=r"(r[0]), "=r"(r[1]), "=r"(r[2]), "=r"(r[3]) : "r"(addr));
}
__device__ __forceinline__ void mma16816(float* d, const uint32_t* a, const uint32_t* b) {
    asm volatile(
        "mma.sync.aligned.m16n8k16.row.col.f32.f16.f16.f32 "
        "{%0,%1,%2,%3}, {%4,%5,%6,%7}, {%8,%9}, {%0,%1,%2,%3};"
        : "+f"(d[0]), "+f"(d[1]), "+f"(d[2]), "+f"(d[3])
        : "r"(a[0]), "r"(a[1]), "r"(a[2]), "r"(a[3]), "r"(b[0]), "r"(b[1]));
}

__device__ __forceinline__ void split2h(float v, __half& a, __half& b) {
    a = __float2half_rn(v);
    b = __float2half_rn(v - __half2float(a));
}
// order-independent float atomic max (monotone int/uint encoding)
__device__ __forceinline__ void atomicMaxF(float* a, float v) {
    if (v >= 0.0f) atomicMax((int*)a, __float_as_int(v));
    else           atomicMin((unsigned int*)a, (unsigned int)__float_as_int(v));
}

// ---------------- HMMA emulated-fp32 GEMM -----------------------------------
// C[128x128] = sum over NPAIR plane pairs Ap[paA[p]] @ Bp[paB[p]]^T
// EPI: 0 = f32 C; 1 = split2 -> 2 fp16 planes; 2 = f32 * rinv[row];
//      3 = f32 * (1/sqrt(DIM)) + atomic row-max (causal-masked on diagonal)
// COMPACT: 1D lower-triangular grid
template <int NA, int NB, int NPAIR, int EPI, bool KLIMF, bool COMPACT, int NSTAGE>
__global__ __launch_bounds__(256, 2)
void hmma_gemm(const __half* __restrict__ A0, const __half* __restrict__ A1,
               const __half* __restrict__ B0, const __half* __restrict__ B1,
               int lda, int ldb, int K,
               float* __restrict__ Cf,
               __half* __restrict__ O0, __half* __restrict__ O1,
               int ldc, const float* __restrict__ rinv,
               float* __restrict__ rowmax)
{
    int bn, bm;
    if (COMPACT) {
        int t = blockIdx.x;
        bm = (int)((sqrtf(8.0f * t + 1.0f) - 1.0f) * 0.5f);
        while ((bm + 1) * (bm + 2) / 2 <= t) bm++;
        while (bm * (bm + 1) / 2 > t) bm--;
        bn = t - bm * (bm + 1) / 2;
    } else {
        bn = blockIdx.x; bm = blockIdx.y;
    }
    const int m0 = bm * 128, n0 = bn * 128;
    const bool diag = COMPACT && (bm == bn);

    constexpr int NPL = NA + NB;
    constexpr uint32_t RSTR = 80;                 // 32 fp16 rows padded to 80B
    constexpr uint32_t PLSZ = 128 * RSTR;         // 10240
    constexpr uint32_t STAGE = NPL * PLSZ;

    extern __shared__ char smem_dyn[];
    const uint32_t sbase = (smem_u32(smem_dyn) + 1023u) & ~1023u;

    const int tid  = threadIdx.x;
    const int lane = tid & 31;
    const int wid  = tid >> 5;
    const int wm   = (wid >> 2) * 64;
    const int wn   = (wid & 3) * 32;

    const __half* pl[NPL];
    pl[0] = A0; if (NA > 1) pl[1] = A1;
    pl[NA] = B0; if (NB > 1) pl[NA + 1] = B1;

    int Kend = K;
    if (KLIMF) { int kl = (bm + 1) * 128; Kend = kl < K ? kl : K; }
    const int nch = Kend >> 5;

    auto load_stage = [&](int c, int buf) {
        const int k0 = c << 5;
        const uint32_t sb = sbase + buf * STAGE;
#pragma unroll
        for (int t = 0; t < NPL * 2; t++) {
            int idx = tid + t * 256;
            int plane = idx >> 9;
            int rem = idx & 511;
            int row = rem >> 2;
            int c4 = rem & 3;
            int rbase = (plane < NA) ? m0 : n0;
            int ld    = (plane < NA) ? lda : ldb;
            const __half* g = pl[plane] + (size_t)(rbase + row) * ld + k0 + c4 * 8;
            cp16(sb + plane * PLSZ + row * RSTR + c4 * 16, g);
        }
        CP_COMMIT();
    };

    float acc[4][4][4];
#pragma unroll
    for (int i = 0; i < 4; i++)
#pragma unroll
        for (int j = 0; j < 4; j++)
#pragma unroll
            for (int q = 0; q < 4; q++) acc[i][j][q] = 0.0f;

    constexpr int paA[3] = {0, 0, 1};
    constexpr int paB[3] = {0, 1, 0};

#pragma unroll
    for (int s = 0; s < NSTAGE; s++)
        if (s < nch) load_stage(s, s);

    for (int c = 0; c < nch; c++) {
        if (NSTAGE == 3) {
            if (c + 3 <= nch) { CP_WAIT2(); }
            else if (c + 2 <= nch) { CP_WAIT1(); }
            else { CP_WAIT0(); }
        } else {
            if (c + 2 <= nch) { CP_WAIT1(); } else { CP_WAIT0(); }
        }
        __syncthreads();

        const uint32_t sb = sbase + (uint32_t)(c % NSTAGE) * STAGE;
        const uint32_t a_row = (uint32_t)(wm + (lane & 15));
        const uint32_t a_kb  = ((uint32_t)(lane >> 4)) << 4;
        const uint32_t b_row = (uint32_t)(wn + ((lane >> 1) & 8) + (lane & 7));
        const uint32_t b_kb  = ((uint32_t)((lane >> 3) & 1)) << 4;

#pragma unroll
        for (int k16 = 0; k16 < 2; k16++) {
            uint32_t bfr[NB][8];
#pragma unroll
            for (int p = 0; p < NB; p++) {
                const uint32_t pbn = sb + (NA + p) * PLSZ + k16 * 32 + b_kb;
#pragma unroll
                for (int nt2 = 0; nt2 < 2; nt2++)
                    ldsm4(&bfr[p][nt2 * 4], pbn + (b_row + nt2 * 16) * RSTR);
            }
#pragma unroll
            for (int ia = 0; ia < NA; ia++) {
                uint32_t af[4][4];
                const uint32_t pbm = sb + ia * PLSZ + k16 * 32 + a_kb;
#pragma unroll
                for (int mt = 0; mt < 4; mt++)
                    ldsm4(af[mt], pbm + (a_row + mt * 16) * RSTR);
#pragma unroll
                for (int p = 0; p < NPAIR; p++) {
                    if (paA[p] != ia) continue;
                    const int ib = paB[p];
#pragma unroll
                    for (int mt = 0; mt < 4; mt++)
#pragma unroll
                        for (int nt = 0; nt < 4; nt++)
                            mma16816(acc[mt][nt], af[mt], &bfr[ib][nt * 2]);
                }
            }
        }
        __syncthreads();
        if (c + NSTAGE < nch) load_stage(c + NSTAGE, c % NSTAGE);
    }

    // ---------------- epilogue ----------------------------------------------
    const float lscale = 0.03125f;   // 1/sqrt(1024)
#pragma unroll
    for (int mt = 0; mt < 4; mt++) {
        float m0r = -3.402823466e38f, m1r = -3.402823466e38f;
        const int gm = m0 + wm + mt * 16 + (lane >> 2);
#pragma unroll
        for (int nt = 0; nt < 4; nt++) {
            const int gn = n0 + wn + nt * 8 + (lane & 3) * 2;
            float c0 = acc[mt][nt][0], c1 = acc[mt][nt][1];
            float c2 = acc[mt][nt][2], c3 = acc[mt][nt][3];
            if (EPI == 0) {
                *reinterpret_cast<float2*>(&Cf[(size_t)gm * ldc + gn]) = make_float2(c0, c1);
                *reinterpret_cast<float2*>(&Cf[(size_t)(gm + 8) * ldc + gn]) = make_float2(c2, c3);
            } else if (EPI == 2) {
                float s0 = rinv[gm], s1 = rinv[gm + 8];
                *reinterpret_cast<float2*>(&Cf[(size_t)gm * ldc + gn]) =
                    make_float2(c0 * s0, c1 * s0);
                *reinterpret_cast<float2*>(&Cf[(size_t)(gm + 8) * ldc + gn]) =
                    make_float2(c2 * s1, c3 * s1);
            } else if (EPI == 3) {
                c0 *= lscale; c1 *= lscale; c2 *= lscale; c3 *= lscale;
                *reinterpret_cast<float2*>(&Cf[(size_t)gm * ldc + gn]) = make_float2(c0, c1);
                *reinterpret_cast<float2*>(&Cf[(size_t)(gm + 8) * ldc + gn]) = make_float2(c2, c3);
                if (!diag || gn     <= gm)     m0r = fmaxf(m0r, c0);
                if (!diag || gn + 1 <= gm)     m0r = fmaxf(m0r, c1);
                if (!diag || gn     <= gm + 8) m1r = fmaxf(m1r, c2);
                if (!diag || gn + 1 <= gm + 8) m1r = fmaxf(m1r, c3);
            } else {
                __half a0, b0, a1, b1;
                __half2 t;
                split2h(c0, a0, b0); split2h(c1, a1, b1);
                t.x = a0; t.y = a1;
                *reinterpret_cast<__half2*>(&O0[(size_t)gm * ldc + gn]) = t;
                t.x = b0; t.y = b1;
                *reinterpret_cast<__half2*>(&O1[(size_t)gm * ldc + gn]) = t;
                split2h(c2, a0, b0); split2h(c3, a1, b1);
                t.x = a0; t.y = a1;
                *reinterpret_cast<__half2*>(&O0[(size_t)(gm + 8) * ldc + gn]) = t;
                t.x = b0; t.y = b1;
                *reinterpret_cast<__half2*>(&O1[(size_t)(gm + 8) * ldc + gn]) = t;
            }
        }
        if (EPI == 3) {
            m0r = fmaxf(m0r, __shfl_xor_sync(0xffffffffu, m0r, 1));
            m0r = fmaxf(m0r, __shfl_xor_sync(0xffffffffu, m0r, 2));
            m1r = fmaxf(m1r, __shfl_xor_sync(0xffffffffu, m1r, 1));
            m1r = fmaxf(m1r, __shfl_xor_sync(0xffffffffu, m1r, 2));
            if ((lane & 3) == 0) {
                atomicMaxF(&rowmax[gm], m0r);
                atomicMaxF(&rowmax[gm + 8], m1r);
            }
        }
    }
}

// ---------------- prep kernels ----------------------------------------------
__global__ void split2_kernel(const float* __restrict__ in, size_t n,
                              __half* __restrict__ o0, __half* __restrict__ o1,
                              float* __restrict__ rowmax)
{
    size_t i = (size_t)blockIdx.x * blockDim.x + threadIdx.x;
    if (i < SEQ) rowmax[i] = __int_as_float(0xFF800000);   // -inf (per-launch reset)
    size_t stride = (size_t)gridDim.x * blockDim.x;
    for (; i < n; i += stride) {
        __half a, b;
        split2h(in[i], a, b);
        o0[i] = a; o1[i] = b;
    }
}

// transpose + split2 of the 3 weight matrices in one launch (z = which W)
__global__ void tsplitW_kernel(const float* __restrict__ Wq, const float* __restrict__ Wk,
                               const float* __restrict__ Wv,
                               __half* __restrict__ q0, __half* __restrict__ q1,
                               __half* __restrict__ k0, __half* __restrict__ k1,
                               __half* __restrict__ v0, __half* __restrict__ v1)
{
    const float* in = (blockIdx.z == 0) ? Wq : (blockIdx.z == 1) ? Wk : Wv;
    __half* o0 = (blockIdx.z == 0) ? q0 : (blockIdx.z == 1) ? k0 : v0;
    __half* o1 = (blockIdx.z == 0) ? q1 : (blockIdx.z == 1) ? k1 : v1;
    __shared__ float t[32][33];
    const int bc = blockIdx.x * 32, br = blockIdx.y * 32;
    const int tx = threadIdx.x, ty = threadIdx.y;   // 32 x 8
#pragma unroll
    for (int i = 0; i < 4; i++)
        t[ty + i * 8][tx] = in[(size_t)(br + ty + i * 8) * DIM + bc + tx];
    __syncthreads();
#pragma unroll
    for (int i = 0; i < 4; i++) {
        float v = t[tx][ty + i * 8];
        size_t o = (size_t)(bc + ty + i * 8) * DIM + br + tx;
        __half a, b;
        split2h(v, a, b);
        o0[o] = a; o1[o] = b;
    }
}

// transpose + split2: V [SEQ, DIM] f32 -> planes [DIM, SEQ] fp16
__global__ void tsplitV_kernel(const float* __restrict__ in,
                               __half* __restrict__ o0, __half* __restrict__ o1)
{
    __shared__ float t[32][33];
    const int bc = blockIdx.x * 32, br = blockIdx.y * 32;
    const int tx = threadIdx.x, ty = threadIdx.y;
#pragma unroll
    for (int i = 0; i < 4; i++)
        t[ty + i * 8][tx] = in[(size_t)(br + ty + i * 8) * DIM + bc + tx];
    __syncthreads();
#pragma unroll
    for (int i = 0; i < 4; i++) {
        float v = t[tx][ty + i * 8];
        size_t o = (size_t)(bc + ty + i * 8) * SEQ + br + tx;
        __half a, b;
        split2h(v, a, b);
        o0[o] = a; o1[o] = b;
    }
}

// single-pass softmax: logits pre-scaled, row max precomputed.
__global__ __launch_bounds__(256)
void softmax_h(const float* __restrict__ P, const float* __restrict__ rowmax,
               __half* __restrict__ Ph, float* __restrict__ rinv)
{
    const int row   = blockIdx.x;
    const int valid = row + 1;
    const int klim  = ((row >> 7) + 1) << 7;
    const float* prow = P + (size_t)row * SEQ;
    const int tid = threadIdx.x;
    __shared__ float red[256];

    const float m = rowmax[row];
    float sum = 0.0f;
    for (int j = tid; j < klim; j += 256) {
        float e = 0.0f;
        if (j < valid) e = __expf(prow[j] - m);
        __half h = __float2half_rn(e);
        Ph[(size_t)row * SEQ + j] = h;
        sum += __half2float(h);
    }
    red[tid] = sum;
    __syncthreads();
#pragma unroll
    for (int s = 128; s > 0; s >>= 1) {
        if (tid < s) red[tid] += red[tid + s];
        __syncthreads();
    }
    if (tid == 0) rinv[row] = 1.0f / red[0];
}

// ---------------- host side --------------------------------------------------
extern "C" void kernel_launch(void* const* d_in, const int* in_sizes, int n_in,
                              void* d_out, int out_size)
{
    const float* x  = (const float*)d_in[0];
    const float* Wq = (const float*)d_in[1];
    const float* Wk = (const float*)d_in[2];
    const float* Wv = (const float*)d_in[3];
    float* out = (float*)d_out;

    __half *x2[2], *Wq2[2], *Wk2[2], *Wv2[2], *Q2[2], *K2[2], *Vt2[2];
    __half *Ph;
    float *V, *P, *rinv, *rowmax;
    for (int i = 0; i < 2; i++) {
        cudaGetSymbolAddress((void**)&x2[i],  g_x2);  x2[i]  += (size_t)i * SEQ * DIM;
        cudaGetSymbolAddress((void**)&Wq2[i], g_Wq2); Wq2[i] += (size_t)i * DIM * DIM;
        cudaGetSymbolAddress((void**)&Wk2[i], g_Wk2); Wk2[i] += (size_t)i * DIM * DIM;
        cudaGetSymbolAddress((void**)&Wv2[i], g_Wv2); Wv2[i] += (size_t)i * DIM * DIM;
        cudaGetSymbolAddress((void**)&Q2[i],  g_Q2);  Q2[i]  += (size_t)i * SEQ * DIM;
        cudaGetSymbolAddress((void**)&K2[i],  g_K2);  K2[i]  += (size_t)i * SEQ * DIM;
        cudaGetSymbolAddress((void**)&Vt2[i], g_Vt2); Vt2[i] += (size_t)i * DIM * SEQ;
    }
    cudaGetSymbolAddress((void**)&Ph,     g_Ph);
    cudaGetSymbolAddress((void**)&V,      g_V);
    cudaGetSymbolAddress((void**)&P,      g_P);
    cudaGetSymbolAddress((void**)&rinv,   g_rinv);
    cudaGetSymbolAddress((void**)&rowmax, g_rowmax);

    auto gemm_proj   = hmma_gemm<2, 2, 3, 1, false, false, 2>;  // Q/K proj
    auto gemm_vproj  = hmma_gemm<1, 2, 2, 0, false, false, 3>;  // V proj (2-pair)
    auto gemm_causal = hmma_gemm<2, 2, 3, 3, false, true,  2>;  // QK^T + rowmax
    auto gemm_pv     = hmma_gemm<1, 2, 2, 2, true,  false, 3>;  // PV

    const int SM42 = 2 * 4 * 10240 + 1024;   // 82944
    const int SM33 = 3 * 3 * 10240 + 1024;   // 93184
    cudaFuncSetAttribute(gemm_proj,   cudaFuncAttributeMaxDynamicSharedMemorySize, SM42);
    cudaFuncSetAttribute(gemm_vproj,  cudaFuncAttributeMaxDynamicSharedMemorySize, SM33);
    cudaFuncSetAttribute(gemm_causal, cudaFuncAttributeMaxDynamicSharedMemorySize, SM42);
    cudaFuncSetAttribute(gemm_pv,     cudaFuncAttributeMaxDynamicSharedMemorySize, SM33);

    // 1) operand splits (also resets rowmax)
    split2_kernel<<<1024, 256>>>(x, (size_t)SEQ * DIM, x2[0], x2[1], rowmax);
    dim3 tb(32, 8);
    tsplitW_kernel<<<dim3(DIM / 32, DIM / 32, 3), tb>>>(Wq, Wk, Wv,
                                                        Wq2[0], Wq2[1], Wk2[0], Wk2[1],
                                                        Wv2[0], Wv2[1]);

    dim3 gProj(DIM / 128, SEQ / 128);     // (8, 32)

    // 2) projections
    gemm_proj<<<gProj, 256, SM42>>>(x2[0], x2[1], Wq2[0], Wq2[1],
                                    DIM, DIM, DIM, nullptr, Q2[0], Q2[1], DIM, nullptr, nullptr);
    gemm_proj<<<gProj, 256, SM42>>>(x2[0], x2[1], Wk2[0], Wk2[1],
                                    DIM, DIM, DIM, nullptr, K2[0], K2[1], DIM, nullptr, nullptr);
    gemm_vproj<<<gProj, 256, SM33>>>(x2[0], nullptr, Wv2[0], Wv2[1],
                                     DIM, DIM, DIM, V, nullptr, nullptr, DIM, nullptr, nullptr);

    // 3) V -> Vt planes
    tsplitV_kernel<<<dim3(DIM / 32, SEQ / 32), tb>>>(V, Vt2[0], Vt2[1]);

    // 4) scaled logits + row maxes (compact lower-triangular grid, 528 CTAs)
    gemm_causal<<<dim3(32 * 33 / 2), 256, SM42>>>(Q2[0], Q2[1], K2[0], K2[1],
                                                  DIM, DIM, DIM, P, nullptr, nullptr,
                                                  SEQ, nullptr, rowmax);

    // 5) single-pass softmax -> fp16 probs + rinv of rounded sum
    softmax_h<<<SEQ, 256>>>(P, rowmax, Ph, rinv);

    // 6) out = (Ph @ V) * rinv, causal K-limit
    gemm_pv<<<gProj, 256, SM33>>>(Ph, nullptr, Vt2[0], Vt2[1],
                                  SEQ, SEQ, SEQ, out, nullptr, nullptr, DIM, rinv, nullptr);
}

// round 11
// speedup vs baseline: 1.5461x; 1.5461x over previous
#include <cuda_runtime.h>
#include <cuda_fp16.h>
#include <cstdint>

// ---------------------------------------------------------------------------
// SelfAttention via mma.sync (HMMA) fp16-emulated-fp32 GEMMs.
// fp32 operand = hi + lo fp16 planes; 3 pair-products (hh,hl,lh) ~2^-22.
// V proj: x_hi @ (Wv_hi + Wv_lo), 2 pairs (dropped x_lo term ~1e-4 rel).
// PV path: P rounded to fp16 (hi only), normalized by the rounded sum ->
// 2 pair-products; error ~1e-4.
// ---------------------------------------------------------------------------

constexpr int SEQ = 4096;
constexpr int DIM = 1024;

__device__ __half g_x2[2][(size_t)SEQ * DIM];
__device__ __half g_Wq2[2][(size_t)DIM * DIM];   // transposed [out][in]
__device__ __half g_Wk2[2][(size_t)DIM * DIM];
__device__ __half g_Wv2[2][(size_t)DIM * DIM];
__device__ __half g_Q2[2][(size_t)SEQ * DIM];
__device__ __half g_K2[2][(size_t)SEQ * DIM];
__device__ float  g_V[(size_t)SEQ * DIM];
__device__ __half g_Vt2[2][(size_t)DIM * SEQ];   // [dim][seq]
__device__ float  g_P[(size_t)SEQ * SEQ];        // logits
__device__ __half g_Ph[(size_t)SEQ * SEQ];       // fp16 unnormalized probs
__device__ float  g_rinv[SEQ];

// ---------------- helpers ---------------------------------------------------
__device__ __forceinline__ uint32_t smem_u32(const void* p) {
    uint32_t a;
    asm("{ .reg .u64 t; cvta.to.shared.u64 t, %1; cvt.u32.u64 %0, t; }"
        : "=r"(a) : "l"(p));
    return a;
}
__device__ __forceinline__ void cp16(uint32_t s, const void* g) {
    asm volatile("cp.async.cg.shared.global [%0], [%1], 16;" :: "r"(s), "l"(g));
}
#define CP_COMMIT() asm volatile("cp.async.commit_group;" ::: "memory")
#define CP_WAIT1()  asm volatile("cp.async.wait_group 1;" ::: "memory")
#define CP_WAIT0()  asm volatile("cp.async.wait_group 0;" ::: "memory")

__device__ __forceinline__ void ldsm4(uint32_t* r, uint32_t addr) {
    asm volatile("ldmatrix.sync.aligned.m8n8.x4.shared.b16 {%0,%1,%2,%3}, [%4];"
                 : "=r"(r[0]), "=r"(r[1]), "=r"(r[2]), "=r"(r[3]) : "r"(addr));
}
__device__ __forceinline__ void mma16816(float* d, const uint32_t* a, const uint32_t* b) {
    asm volatile(
        "mma.sync.aligned.m16n8k16.row.col.f32.f16.f16.f32 "
        "{%0,%1,%2,%3}, {%4,%5,%6,%7}, {%8,%9}, {%0,%1,%2,%3};"
        : "+f"(d[0]), "+f"(d[1]), "+f"(d[2]), "+f"(d[3])
        : "r"(a[0]), "r"(a[1]), "r"(a[2]), "r"(a[3]), "r"(b[0]), "r"(b[1]));
}

__device__ __forceinline__ void split2h(float v, __half& a, __half& b) {
    a = __float2half_rn(v);
    b = __float2half_rn(v - __half2float(a));
}

// ---------------- HMMA emulated-fp32 GEMM -----------------------------------
// C[128x128] = sum over NPAIR plane pairs Ap[paA[p]] @ Bp[paB[p]]^T
// A planes M-K-major fp16, B planes N-K-major fp16.
// EPI: 0 = f32 C, 1 = split2 -> 2 fp16 planes, 2 = f32 * rinv[row]
// COMPACT: 1D lower-triangular grid (QK^T causal)
template <int NA, int NB, int NPAIR, int EPI, bool KLIMF, bool COMPACT>
__global__ __launch_bounds__(256, 2)
void hmma_gemm(const __half* __restrict__ A0, const __half* __restrict__ A1,
               const __half* __restrict__ B0, const __half* __restrict__ B1,
               int lda, int ldb, int K,
               float* __restrict__ Cf,
               __half* __restrict__ O0, __half* __restrict__ O1,
               int ldc, const float* __restrict__ rinv)
{
    int bn, bm;
    if (COMPACT) {
        int t = blockIdx.x;
        bm = (int)((sqrtf(8.0f * t + 1.0f) - 1.0f) * 0.5f);
        while ((bm + 1) * (bm + 2) / 2 <= t) bm++;
        while (bm * (bm + 1) / 2 > t) bm--;
        bn = t - bm * (bm + 1) / 2;
    } else {
        bn = blockIdx.x; bm = blockIdx.y;
    }
    const int m0 = bm * 128, n0 = bn * 128;

    constexpr int NPL = NA + NB;
    constexpr uint32_t RSTR = 80;                 // 32 fp16 rows padded to 80B
    constexpr uint32_t PLSZ = 128 * RSTR;         // 10240
    constexpr uint32_t STAGE = NPL * PLSZ;

    extern __shared__ char smem_dyn[];
    const uint32_t sbase = (smem_u32(smem_dyn) + 1023u) & ~1023u;

    const int tid  = threadIdx.x;
    const int lane = tid & 31;
    const int wid  = tid >> 5;
    const int wm   = (wid >> 2) * 64;   // warp M offset
    const int wn   = (wid & 3) * 32;    // warp N offset

    const __half* pl[NPL];
    pl[0] = A0; if (NA > 1) pl[1] = A1;
    pl[NA] = B0; if (NB > 1) pl[NA + 1] = B1;

    int Kend = K;
    if (KLIMF) { int kl = (bm + 1) * 128; Kend = kl < K ? kl : K; }
    const int nch = Kend >> 5;   // 32-k chunks

    auto load_stage = [&](int c, int buf) {
        const int k0 = c << 5;
        const uint32_t sb = sbase + buf * STAGE;
#pragma unroll
        for (int t = 0; t < NPL * 2; t++) {
            int idx = tid + t * 256;
            int plane = idx >> 9;
            int rem = idx & 511;
            int row = rem >> 2;
            int c4 = rem & 3;
            int rbase = (plane < NA) ? m0 : n0;
            int ld    = (plane < NA) ? lda : ldb;
            const __half* g = pl[plane] + (size_t)(rbase + row) * ld + k0 + c4 * 8;
            cp16(sb + plane * PLSZ + row * RSTR + c4 * 16, g);
        }
        CP_COMMIT();
    };

    float acc[4][4][4];
#pragma unroll
    for (int i = 0; i < 4; i++)
#pragma unroll
        for (int j = 0; j < 4; j++)
#pragma unroll
            for (int q = 0; q < 4; q++) acc[i][j][q] = 0.0f;

    // pair tables: 3-pair = (0,0),(0,1),(1,0); 2-pair = (0,0),(0,1)
    constexpr int paA[3] = {0, 0, 1};
    constexpr int paB[3] = {0, 1, 0};

    load_stage(0, 0);
    if (nch > 1) load_stage(1, 1);

    for (int c = 0; c < nch; c++) {
        if (c + 1 < nch) { CP_WAIT1(); } else { CP_WAIT0(); }
        __syncthreads();

        const uint32_t sb = sbase + (c & 1) * STAGE;
        const uint32_t a_row = (uint32_t)(wm + (lane & 15));
        const uint32_t a_kb  = ((uint32_t)(lane >> 4)) << 4;
        const uint32_t b_row = (uint32_t)(wn + ((lane >> 1) & 8) + (lane & 7));
        const uint32_t b_kb  = ((uint32_t)((lane >> 3) & 1)) << 4;

#pragma unroll
        for (int k16 = 0; k16 < 2; k16++) {
            // all B-plane fragments (NB*8 regs)
            uint32_t bfr[NB][8];
#pragma unroll
            for (int p = 0; p < NB; p++) {
                const uint32_t pbn = sb + (NA + p) * PLSZ + k16 * 32 + b_kb;
#pragma unroll
                for (int nt2 = 0; nt2 < 2; nt2++)
                    ldsm4(&bfr[p][nt2 * 4], pbn + (b_row + nt2 * 16) * RSTR);
            }
            // A planes one at a time (16 regs reused) to bound live registers
#pragma unroll
            for (int ia = 0; ia < NA; ia++) {
                uint32_t af[4][4];
                const uint32_t pbm = sb + ia * PLSZ + k16 * 32 + a_kb;
#pragma unroll
                for (int mt = 0; mt < 4; mt++)
                    ldsm4(af[mt], pbm + (a_row + mt * 16) * RSTR);
#pragma unroll
                for (int p = 0; p < NPAIR; p++) {
                    if (paA[p] != ia) continue;
                    const int ib = paB[p];
#pragma unroll
                    for (int mt = 0; mt < 4; mt++)
#pragma unroll
                        for (int nt = 0; nt < 4; nt++)
                            mma16816(acc[mt][nt], af[mt], &bfr[ib][nt * 2]);
                }
            }
        }
        __syncthreads();
        if (c + 2 < nch) load_stage(c + 2, c & 1);
    }

    // ---------------- epilogue ----------------------------------------------
#pragma unroll
    for (int mt = 0; mt < 4; mt++) {
#pragma unroll
        for (int nt = 0; nt < 4; nt++) {
            const int gm = m0 + wm + mt * 16 + (lane >> 2);
            const int gn = n0 + wn + nt * 8 + (lane & 3) * 2;
            float c0 = acc[mt][nt][0], c1 = acc[mt][nt][1];
            float c2 = acc[mt][nt][2], c3 = acc[mt][nt][3];
            if (EPI == 0) {
                *reinterpret_cast<float2*>(&Cf[(size_t)gm * ldc + gn]) = make_float2(c0, c1);
                *reinterpret_cast<float2*>(&Cf[(size_t)(gm + 8) * ldc + gn]) = make_float2(c2, c3);
            } else if (EPI == 2) {
                float s0 = rinv[gm], s1 = rinv[gm + 8];
                *reinterpret_cast<float2*>(&Cf[(size_t)gm * ldc + gn]) =
                    make_float2(c0 * s0, c1 * s0);
                *reinterpret_cast<float2*>(&Cf[(size_t)(gm + 8) * ldc + gn]) =
                    make_float2(c2 * s1, c3 * s1);
            } else {
                __half a0, b0, a1, b1;
                __half2 t;
                split2h(c0, a0, b0); split2h(c1, a1, b1);
                t.x = a0; t.y = a1;
                *reinterpret_cast<__half2*>(&O0[(size_t)gm * ldc + gn]) = t;
                t.x = b0; t.y = b1;
                *reinterpret_cast<__half2*>(&O1[(size_t)gm * ldc + gn]) = t;
                split2h(c2, a0, b0); split2h(c3, a1, b1);
                t.x = a0; t.y = a1;
                *reinterpret_cast<__half2*>(&O0[(size_t)(gm + 8) * ldc + gn]) = t;
                t.x = b0; t.y = b1;
                *reinterpret_cast<__half2*>(&O1[(size_t)(gm + 8) * ldc + gn]) = t;
            }
        }
    }
}

// ---------------- prep kernels ----------------------------------------------
__global__ void split2_kernel(const float* __restrict__ in, size_t n,
                              __half* __restrict__ o0, __half* __restrict__ o1)
{
    size_t i = (size_t)blockIdx.x * blockDim.x + threadIdx.x;
    size_t stride = (size_t)gridDim.x * blockDim.x;
    for (; i < n; i += stride) {
        __half a, b;
        split2h(in[i], a, b);
        o0[i] = a; o1[i] = b;
    }
}

// transpose + split2: in [R, C] f32 -> planes [C, R] fp16
__global__ void tsplit2_kernel(const float* __restrict__ in, int R, int C,
                               __half* __restrict__ o0, __half* __restrict__ o1)
{
    __shared__ float t[32][33];
    const int bc = blockIdx.x * 32, br = blockIdx.y * 32;
    const int tx = threadIdx.x, ty = threadIdx.y;   // 32 x 8
#pragma unroll
    for (int i = 0; i < 4; i++)
        t[ty + i * 8][tx] = in[(size_t)(br + ty + i * 8) * C + bc + tx];
    __syncthreads();
#pragma unroll
    for (int i = 0; i < 4; i++) {
        float v = t[tx][ty + i * 8];
        size_t o = (size_t)(bc + ty + i * 8) * R + br + tx;
        __half a, b;
        split2h(v, a, b);
        o0[o] = a; o1[o] = b;
    }
}

// causal softmax: exp -> fp16 (hi only); rinv = 1 / sum(rounded values) so the
// PV normalization cancels the systematic rounding of P.
__global__ __launch_bounds__(256)
void softmax_h(const float* __restrict__ P, __half* __restrict__ Ph,
               float* __restrict__ rinv)
{
    const int row   = blockIdx.x;
    const int valid = row + 1;
    const int klim  = ((row >> 7) + 1) << 7;
    const float* prow = P + (size_t)row * SEQ;
    const int tid = threadIdx.x;
    __shared__ float red[256];

    float m = -3.402823466e38f;
    for (int j = tid; j < valid; j += 256) m = fmaxf(m, prow[j]);
    red[tid] = m;
    __syncthreads();
#pragma unroll
    for (int s = 128; s > 0; s >>= 1) {
        if (tid < s) red[tid] = fmaxf(red[tid], red[tid + s]);
        __syncthreads();
    }
    m = red[0];
    __syncthreads();

    const float inv_sqrt_d = 0.03125f;
    float sum = 0.0f;
    for (int j = tid; j < klim; j += 256) {
        float e = 0.0f;
        if (j < valid) e = __expf((prow[j] - m) * inv_sqrt_d);
        __half h = __float2half_rn(e);
        Ph[(size_t)row * SEQ + j] = h;
        sum += __half2float(h);
    }
    red[tid] = sum;
    __syncthreads();
#pragma unroll
    for (int s = 128; s > 0; s >>= 1) {
        if (tid < s) red[tid] += red[tid + s];
        __syncthreads();
    }
    if (tid == 0) rinv[row] = 1.0f / red[0];
}

// ---------------- host side --------------------------------------------------
extern "C" void kernel_launch(void* const* d_in, const int* in_sizes, int n_in,
                              void* d_out, int out_size)
{
    const float* x  = (const float*)d_in[0];
    const float* Wq = (const float*)d_in[1];
    const float* Wk = (const float*)d_in[2];
    const float* Wv = (const float*)d_in[3];
    float* out = (float*)d_out;

    __half *x2[2], *Wq2[2], *Wk2[2], *Wv2[2], *Q2[2], *K2[2], *Vt2[2];
    __half *Ph;
    float *V, *P, *rinv;
    for (int i = 0; i < 2; i++) {
        cudaGetSymbolAddress((void**)&x2[i],  g_x2);  x2[i]  += (size_t)i * SEQ * DIM;
        cudaGetSymbolAddress((void**)&Wq2[i], g_Wq2); Wq2[i] += (size_t)i * DIM * DIM;
        cudaGetSymbolAddress((void**)&Wk2[i], g_Wk2); Wk2[i] += (size_t)i * DIM * DIM;
        cudaGetSymbolAddress((void**)&Wv2[i], g_Wv2); Wv2[i] += (size_t)i * DIM * DIM;
        cudaGetSymbolAddress((void**)&Q2[i],  g_Q2);  Q2[i]  += (size_t)i * SEQ * DIM;
        cudaGetSymbolAddress((void**)&K2[i],  g_K2);  K2[i]  += (size_t)i * SEQ * DIM;
        cudaGetSymbolAddress((void**)&Vt2[i], g_Vt2); Vt2[i] += (size_t)i * DIM * SEQ;
    }
    cudaGetSymbolAddress((void**)&Ph,   g_Ph);
    cudaGetSymbolAddress((void**)&V,    g_V);
    cudaGetSymbolAddress((void**)&P,    g_P);
    cudaGetSymbolAddress((void**)&rinv, g_rinv);

    auto gemm_proj   = hmma_gemm<2, 2, 3, 1, false, false>;  // Q/K proj -> fp16 planes
    auto gemm_vproj  = hmma_gemm<1, 2, 2, 0, false, false>;  // V proj (2-pair, x_hi only)
    auto gemm_causal = hmma_gemm<2, 2, 3, 0, false, true>;   // QK^T -> f32 logits (compact)
    auto gemm_pv     = hmma_gemm<1, 2, 2, 2, true,  false>;  // PV -> out (K-limit)

    const int SM4 = 2 * 4 * 10240 + 1024;   // 82944
    const int SM3 = 2 * 3 * 10240 + 1024;   // 62464
    cudaFuncSetAttribute(gemm_proj,   cudaFuncAttributeMaxDynamicSharedMemorySize, SM4);
    cudaFuncSetAttribute(gemm_vproj,  cudaFuncAttributeMaxDynamicSharedMemorySize, SM3);
    cudaFuncSetAttribute(gemm_causal, cudaFuncAttributeMaxDynamicSharedMemorySize, SM4);
    cudaFuncSetAttribute(gemm_pv,     cudaFuncAttributeMaxDynamicSharedMemorySize, SM3);

    // 1) operand splits
    split2_kernel<<<1024, 256>>>(x, (size_t)SEQ * DIM, x2[0], x2[1]);
    dim3 tb(32, 8);
    tsplit2_kernel<<<dim3(DIM / 32, DIM / 32), tb>>>(Wq, DIM, DIM, Wq2[0], Wq2[1]);
    tsplit2_kernel<<<dim3(DIM / 32, DIM / 32), tb>>>(Wk, DIM, DIM, Wk2[0], Wk2[1]);
    tsplit2_kernel<<<dim3(DIM / 32, DIM / 32), tb>>>(Wv, DIM, DIM, Wv2[0], Wv2[1]);

    dim3 gProj(DIM / 128, SEQ / 128);     // (8, 32)

    // 2) projections
    gemm_proj<<<gProj, 256, SM4>>>(x2[0], x2[1], Wq2[0], Wq2[1],
                                   DIM, DIM, DIM, nullptr, Q2[0], Q2[1], DIM, nullptr);
    gemm_proj<<<gProj, 256, SM4>>>(x2[0], x2[1], Wk2[0], Wk2[1],
                                   DIM, DIM, DIM, nullptr, K2[0], K2[1], DIM, nullptr);
    gemm_vproj<<<gProj, 256, SM3>>>(x2[0], nullptr, Wv2[0], Wv2[1],
                                    DIM, DIM, DIM, V, nullptr, nullptr, DIM, nullptr);

    // 3) V -> Vt (split2, transposed)
    tsplit2_kernel<<<dim3(DIM / 32, SEQ / 32), tb>>>(V, SEQ, DIM, Vt2[0], Vt2[1]);

    // 4) logits: compact lower-triangular grid (528 CTAs)
    gemm_causal<<<dim3(32 * 33 / 2), 256, SM4>>>(Q2[0], Q2[1], K2[0], K2[1],
                                                 DIM, DIM, DIM, P, nullptr, nullptr, SEQ, nullptr);

    // 5) softmax -> fp16 probs + rinv of rounded sum
    softmax_h<<<SEQ, 256>>>(P, Ph, rinv);

    // 6) out = (Ph @ V) * rinv, causal K-limit; A = single plane Ph
    gemm_pv<<<gProj, 256, SM3>>>(Ph, nullptr, Vt2[0], Vt2[1],
                                 SEQ, SEQ, SEQ, out, nullptr, nullptr, DIM, rinv);
}